// round 1
// baseline (speedup 1.0000x reference)
#include <cuda_runtime.h>
#include <cuda_bf16.h>
#include <cstdint>

// DySample: x(8,256,64,64), W_off(32,256), b_off(32) -> out(8,256,128,128), fp32.
// Key identity: sample position ix = w + (0.25*off_x + ipx), iy = h + (0.25*off_y + ipy)
// (the grid normalization cancels), with border clamp bilinear on the 64x64 group plane.
// Channel mapping: for output pixel (b, g, oy=2h+ry, ox=2w+rx):
//   j = g*4 + ry*2 + rx ; offset channels o_x = j, o_y = 16 + j
//   init pos: x uses hpos[rx], y uses hpos[ry], hpos = {-0.25, +0.25}
// Gathered input channel for output channel c = g*64 + cl is the same c.

#define Bn 8
#define Cn 256
#define Hn 64
#define Wn 64
#define Gn 4
#define On 32
#define CGn 64   // channels per group
#define OH 128
#define OW 128

__device__ __forceinline__ void ffma2(unsigned long long &d, unsigned long long a, unsigned long long b) {
    asm("fma.rn.f32x2 %0, %1, %2, %0;" : "+l"(d) : "l"(a), "l"(b));
}
__device__ __forceinline__ unsigned long long pack2(float lo, float hi) {
    unsigned long long r;
    asm("mov.b64 %0, {%1, %2};" : "=l"(r) : "f"(lo), "f"(hi));
    return r;
}
__device__ __forceinline__ float sum2(unsigned long long v) {
    float lo, hi;
    asm("mov.b64 {%0, %1}, %2;" : "=f"(lo), "=f"(hi) : "l"(v));
    return lo + hi;
}

__global__ __launch_bounds__(256) void dysample_kernel(
    const float* __restrict__ x,
    const float* __restrict__ Woff,
    const float* __restrict__ boff,
    float* __restrict__ out)
{
    __shared__ float Ws[On][Cn];   // 32 KB
    __shared__ float xs[4][Wn];    // 1 KB
    __shared__ float sx[16][Wn];   // 4 KB  sample x-coords
    __shared__ float sy[16][Wn];   // 4 KB  sample y-coords

    const int tid = threadIdx.x;
    const int h = blockIdx.x;
    const int b = blockIdx.y;

    // ---- stage W_off into smem (float4) ----
    {
        const float4* Wg = (const float4*)Woff;
        float4* Wsm = (float4*)&Ws[0][0];
        #pragma unroll
        for (int i = 0; i < (On * Cn / 4) / 256; i++) {
            Wsm[tid + i * 256] = Wg[tid + i * 256];
        }
    }

    const int w  = tid & 63;
    const int oq = tid >> 6;       // 0..3, each handles 8 output channels
    const int ci = tid >> 6;       // staging row for x

    unsigned long long acc[8];
    #pragma unroll
    for (int k = 0; k < 8; k++) acc[k] = 0ull;  // bits of (0.f, 0.f)

    const float* xrow = x + ((size_t)b * Cn * Hn * Wn) + (size_t)h * Wn;

    __syncthreads();

    // ---- Phase 1: offset GEMM: acc[o] = sum_c W[o][c] * x[b,c,h,w] ----
    for (int c0 = 0; c0 < Cn; c0 += 4) {
        xs[ci][w] = xrow[(size_t)(c0 + ci) * (Hn * Wn) + w];
        __syncthreads();
        unsigned long long xp0 = pack2(xs[0][w], xs[1][w]);
        unsigned long long xp1 = pack2(xs[2][w], xs[3][w]);
        #pragma unroll
        for (int k = 0; k < 8; k++) {
            const int o = oq * 8 + k;
            float4 wv = *(const float4*)&Ws[o][c0];
            ffma2(acc[k], pack2(wv.x, wv.y), xp0);
            ffma2(acc[k], pack2(wv.z, wv.w), xp1);
        }
        __syncthreads();
    }

    // ---- Phase 2: offsets -> sample coordinates in smem ----
    #pragma unroll
    for (int k = 0; k < 8; k++) {
        const int o = oq * 8 + k;
        float val = sum2(acc[k]) + __ldg(&boff[o]);
        float off = 0.25f * val;
        if (o < 16) {
            const int j = o;
            const float ip = (j & 1) ? 0.25f : -0.25f;   // rx
            sx[j][w] = (float)w + off + ip;
        } else {
            const int j = o - 16;
            const float ip = ((j >> 1) & 1) ? 0.25f : -0.25f;  // ry
            sy[j][w] = (float)h + off + ip;
        }
    }
    __syncthreads();

    // ---- Phase 3: bilinear gather + store ----
    const int ox    = tid & 127;
    const int chalf = tid >> 7;      // 0..1 -> channels chalf*32 .. +31 within group
    const int wq = ox >> 1;
    const int rx = ox & 1;

    #pragma unroll
    for (int ry = 0; ry < 2; ry++) {
        const int oy = 2 * h + ry;
        #pragma unroll
        for (int g = 0; g < Gn; g++) {
            const int j = g * 4 + ry * 2 + rx;
            const float ix = sx[j][wq];
            const float iy = sy[j][wq];
            const float xf = floorf(ix);
            const float yf = floorf(iy);
            const float wx = ix - xf;
            const float wy = iy - yf;
            const int xi = (int)xf;
            const int yi = (int)yf;
            const int x0 = min(max(xi, 0), Wn - 1);
            const int x1 = min(max(xi + 1, 0), Wn - 1);
            const int y0 = min(max(yi, 0), Hn - 1);
            const int y1 = min(max(yi + 1, 0), Hn - 1);
            const float w00 = (1.f - wx) * (1.f - wy);
            const float w01 = wx * (1.f - wy);
            const float w10 = (1.f - wx) * wy;
            const float w11 = wx * wy;
            const int o00 = y0 * Wn + x0;
            const int o01 = y0 * Wn + x1;
            const int o10 = y1 * Wn + x0;
            const int o11 = y1 * Wn + x1;

            const int cbase = b * Cn + g * CGn + chalf * 32;
            const float* xp = x + (size_t)cbase * (Hn * Wn);
            float* op = out + (((size_t)cbase * OH + oy) * OW + ox);

            #pragma unroll 8
            for (int k = 0; k < 32; k++) {
                const float* p = xp + (size_t)k * (Hn * Wn);
                float v = w00 * __ldg(p + o00) + w01 * __ldg(p + o01)
                        + w10 * __ldg(p + o10) + w11 * __ldg(p + o11);
                op[(size_t)k * (OH * OW)] = v;
            }
        }
    }
}

extern "C" void kernel_launch(void* const* d_in, const int* in_sizes, int n_in,
                              void* d_out, int out_size) {
    const float* x    = (const float*)d_in[0];
    const float* Woff = (const float*)d_in[1];
    const float* boff = (const float*)d_in[2];
    float* out = (float*)d_out;

    dim3 grid(Hn, Bn);
    dysample_kernel<<<grid, 256>>>(x, Woff, boff, out);
}

// round 2
// speedup vs baseline: 1.5554x; 1.5554x over previous
#include <cuda_runtime.h>
#include <cuda_bf16.h>
#include <cstdint>

// DySample: x(8,256,64,64), W_off(32,256), b_off(32) -> out(8,256,128,128), fp32.
// Two-kernel split:
//   A: offsets = W_off @ x + b_off, folded into final sample coordinates,
//      written to 4MB scratch (coord[b][o][h*64+w]).  o<16: x-coords, o>=16: y-coords.
//   B: bilinear border-clamped gather + coalesced store.
// Identity: ix = w + (0.25*off_x + ipx), iy = h + (0.25*off_y + ipy);
//   j = g*4 + ry*2 + rx; o_x = j, o_y = 16 + j; ipx = (j&1)?+.25:-.25, ipy = ((j>>1)&1)?+.25:-.25

#define Bn 8
#define Cn 256
#define Hn 64
#define Wn 64
#define Gn 4
#define NPOS 4096   // Hn*Wn
#define OH 128
#define OW 128

__device__ float d_coord[Bn * 32 * NPOS];   // 4 MB scratch

__device__ __forceinline__ void ffma2(unsigned long long &d, unsigned long long a, unsigned long long b) {
    asm("fma.rn.f32x2 %0, %1, %2, %0;" : "+l"(d) : "l"(a), "l"(b));
}
__device__ __forceinline__ unsigned long long pack2(float lo, float hi) {
    unsigned long long r;
    asm("mov.b64 %0, {%1, %2};" : "=l"(r) : "f"(lo), "f"(hi));
    return r;
}
__device__ __forceinline__ void unpack2(unsigned long long v, float &lo, float &hi) {
    asm("mov.b64 {%0, %1}, %2;" : "=f"(lo), "=f"(hi) : "l"(v));
}

// ---------------- Kernel A: offset GEMM + coordinate epilogue ----------------
// grid (16, 8), 256 threads; thread owns one spatial position.
__global__ __launch_bounds__(256) void offset_kernel(
    const float* __restrict__ x,
    const float* __restrict__ Woff,
    const float* __restrict__ boff)
{
    __shared__ unsigned long long Wp[16][256];   // (W[p][c], W[p+16][c])  32 KB

    const int tid = threadIdx.x;
    const int b   = blockIdx.y;
    const int pos = blockIdx.x * 256 + tid;

    // stage packed W: pair channel p (x-offset) with p+16 (y-offset)
    #pragma unroll
    for (int i = 0; i < 16; i++) {
        const int idx = i * 256 + tid;
        const int p = idx >> 8, c = idx & 255;
        Wp[p][c] = pack2(Woff[p * Cn + c], Woff[(p + 16) * Cn + c]);
    }
    __syncthreads();

    unsigned long long acc[16];
    #pragma unroll
    for (int p = 0; p < 16; p++) acc[p] = 0ull;

    const float* xb = x + (size_t)b * Cn * NPOS + pos;

    #pragma unroll 8
    for (int c = 0; c < Cn; c++) {
        const float xv = __ldg(xb + (size_t)c * NPOS);
        const unsigned long long xp = pack2(xv, xv);
        #pragma unroll
        for (int p = 0; p < 16; p++) ffma2(acc[p], Wp[p][c], xp);
    }

    const int w = pos & 63;
    const int h = pos >> 6;
    #pragma unroll
    for (int p = 0; p < 16; p++) {
        float lo, hi;
        unpack2(acc[p], lo, hi);
        const float ipx = (p & 1) ? 0.25f : -0.25f;
        const float ipy = ((p >> 1) & 1) ? 0.25f : -0.25f;
        const float cx = (float)w + 0.25f * (lo + __ldg(boff + p)) + ipx;
        const float cy = (float)h + 0.25f * (hi + __ldg(boff + p + 16)) + ipy;
        d_coord[((size_t)(b * 32 + p)) * NPOS + pos]      = cx;
        d_coord[((size_t)(b * 32 + p + 16)) * NPOS + pos] = cy;
    }
}

// ---------------- Kernel B: bilinear gather + store ----------------
// grid (64, 8), 512 threads. Block = one (b, h): 256 chan x 2 rows x 128 cols.
__global__ __launch_bounds__(512) void gather_kernel(
    const float* __restrict__ x,
    float* __restrict__ out)
{
    __shared__ float sx[16][Wn];   // 4 KB
    __shared__ float sy[16][Wn];   // 4 KB

    const int tid = threadIdx.x;
    const int h = blockIdx.x;
    const int b = blockIdx.y;

    // load coordinates for this (b, h)
    #pragma unroll
    for (int i = 0; i < 4; i++) {
        const int idx = i * 512 + tid;           // 0..2047
        const int o = idx >> 6, w = idx & 63;
        const float v = d_coord[((size_t)(b * 32 + o)) * NPOS + (h << 6) + w];
        if (o < 16) sx[o][w] = v;
        else        sy[o - 16][w] = v;
    }
    __syncthreads();

    const int ox = tid & 127;
    const int q  = tid >> 7;        // 0..3: 16-channel slab within a group
    const int wq = ox >> 1;
    const int rx = ox & 1;

    #pragma unroll
    for (int ry = 0; ry < 2; ry++) {
        const int oy = 2 * h + ry;
        #pragma unroll
        for (int g = 0; g < Gn; g++) {
            const int j = g * 4 + ry * 2 + rx;
            const float ix = sx[j][wq];
            const float iy = sy[j][wq];
            const float xf = floorf(ix);
            const float yf = floorf(iy);
            const float wx = ix - xf;
            const float wy = iy - yf;
            const int xi = (int)xf;
            const int yi = (int)yf;
            const int x0 = min(max(xi, 0), Wn - 1);
            const int x1 = min(max(xi + 1, 0), Wn - 1);
            const int y0 = min(max(yi, 0), Hn - 1);
            const int y1 = min(max(yi + 1, 0), Hn - 1);
            const float w00 = (1.f - wx) * (1.f - wy);
            const float w01 = wx * (1.f - wy);
            const float w10 = (1.f - wx) * wy;
            const float w11 = wx * wy;
            const int o00 = y0 * Wn + x0;
            const int o01 = y0 * Wn + x1;
            const int o10 = y1 * Wn + x0;
            const int o11 = y1 * Wn + x1;

            const int cbase = b * Cn + g * 64 + q * 16;
            const float* xp = x + (size_t)cbase * NPOS;
            float* op = out + (((size_t)cbase * OH + oy) * OW + ox);

            #pragma unroll
            for (int k = 0; k < 16; k++) {
                const float* p = xp + (size_t)k * NPOS;
                const float v = w00 * __ldg(p + o00) + w01 * __ldg(p + o01)
                              + w10 * __ldg(p + o10) + w11 * __ldg(p + o11);
                op[(size_t)k * (OH * OW)] = v;
            }
        }
    }
}

extern "C" void kernel_launch(void* const* d_in, const int* in_sizes, int n_in,
                              void* d_out, int out_size) {
    const float* x    = (const float*)d_in[0];
    const float* Woff = (const float*)d_in[1];
    const float* boff = (const float*)d_in[2];
    float* out = (float*)d_out;

    dim3 gridA(16, Bn);
    offset_kernel<<<gridA, 256>>>(x, Woff, boff);

    dim3 gridB(Hn, Bn);
    gather_kernel<<<gridB, 512>>>(x, out);
}

// round 3
// speedup vs baseline: 1.9329x; 1.2427x over previous
#include <cuda_runtime.h>
#include <cuda_bf16.h>
#include <cstdint>

// DySample: x(8,256,64,64), W_off(32,256), b_off(32) -> out(8,256,128,128), fp32.
//   A: offsets = W_off @ x + b_off folded into final sample coords -> 4MB scratch.
//   B: bilinear border-clamped gather + coalesced store.
// ix = w + (0.25*off_x + ipx), iy = h + (0.25*off_y + ipy);
// j = g*4 + ry*2 + rx; o_x = j, o_y = 16 + j; ipx = (j&1)?+.25:-.25, ipy = ((j>>1)&1)?+.25:-.25

#define Bn 8
#define Cn 256
#define Hn 64
#define Wn 64
#define Gn 4
#define NPOS 4096
#define OH 128
#define OW 128

typedef unsigned long long ull;

__device__ float d_coord[Bn * 32 * NPOS];   // 4 MB scratch

__device__ __forceinline__ void ffma2(ull &d, ull a, ull b) {
    asm("fma.rn.f32x2 %0, %1, %2, %0;" : "+l"(d) : "l"(a), "l"(b));
}
__device__ __forceinline__ ull pack2(float lo, float hi) {
    ull r;
    asm("mov.b64 %0, {%1, %2};" : "=l"(r) : "f"(lo), "f"(hi));
    return r;
}
__device__ __forceinline__ void unpack2(ull v, float &lo, float &hi) {
    asm("mov.b64 {%0, %1}, %2;" : "=f"(lo), "=f"(hi) : "l"(v));
}

// ---------------- Kernel A: offset GEMM, channel-split x4 ----------------
// grid (64, 8), 256 threads. Block = 64 positions; thread = (pos, cq), cq owns 64 channels.
__global__ __launch_bounds__(256) void offset_kernel(
    const float* __restrict__ x,
    const float* __restrict__ Woff,
    const float* __restrict__ boff)
{
    // overlay: Wp (32KB) used in main loop; red (34KB) used after
    __shared__ __align__(16) char sraw[4 * 64 * 17 * 8];
    ull (*Wp)[256] = reinterpret_cast<ull(*)[256]>(sraw);
    float2 (*red)[64][17] = reinterpret_cast<float2(*)[64][17]>(sraw);

    const int tid  = threadIdx.x;
    const int b    = blockIdx.y;
    const int posl = tid & 63;
    const int cq   = tid >> 6;           // 0..3 (warp-uniform)
    const int gpos = blockIdx.x * 64 + posl;

    // stage packed W: pair offset-channel p (x) with p+16 (y)
    #pragma unroll
    for (int i = 0; i < 16; i++) {
        const int idx = i * 256 + tid;
        const int p = idx >> 8, c = idx & 255;
        Wp[p][c] = pack2(Woff[p * Cn + c], Woff[(p + 16) * Cn + c]);
    }
    __syncthreads();

    ull acc[16];
    #pragma unroll
    for (int p = 0; p < 16; p++) acc[p] = 0ull;

    const float* xb = x + (size_t)b * Cn * NPOS + gpos;
    const int c0 = cq * 64;

    #pragma unroll 4
    for (int cc = 0; cc < 64; cc += 2) {
        const int c = c0 + cc;
        const float xv0 = __ldg(xb + (size_t)c * NPOS);
        const float xv1 = __ldg(xb + (size_t)(c + 1) * NPOS);
        const ull xp0 = pack2(xv0, xv0);
        const ull xp1 = pack2(xv1, xv1);
        #pragma unroll
        for (int p = 0; p < 16; p++) {
            ulonglong2 wv = *(const ulonglong2*)&Wp[p][c];
            ffma2(acc[p], wv.x, xp0);
            ffma2(acc[p], wv.y, xp1);
        }
    }
    __syncthreads();                      // Wp dead; reuse smem as red

    #pragma unroll
    for (int p = 0; p < 16; p++) {
        float lo, hi;
        unpack2(acc[p], lo, hi);
        red[cq][posl][p] = make_float2(lo, hi);
    }
    __syncthreads();

    // thread (pos, cq) finishes packs p = cq*4 .. cq*4+3
    const int w = gpos & 63;
    const int h = gpos >> 6;
    #pragma unroll
    for (int k = 0; k < 4; k++) {
        const int p = cq * 4 + k;
        float2 s = red[0][posl][p];
        #pragma unroll
        for (int q = 1; q < 4; q++) {
            float2 t = red[q][posl][p];
            s.x += t.x; s.y += t.y;
        }
        const float ipx = (p & 1) ? 0.25f : -0.25f;
        const float ipy = ((p >> 1) & 1) ? 0.25f : -0.25f;
        const float cx = (float)w + 0.25f * (s.x + __ldg(boff + p)) + ipx;
        const float cy = (float)h + 0.25f * (s.y + __ldg(boff + p + 16)) + ipy;
        d_coord[(size_t)(b * 32 + p) * NPOS + gpos]      = cx;
        d_coord[(size_t)(b * 32 + p + 16) * NPOS + gpos] = cy;
    }
}

// ---------------- Kernel B: bilinear gather + store ----------------
// grid (64, 8, 2), 256 threads. Block = (b, h, chan-half); batched loads for MLP.
__global__ __launch_bounds__(256, 2) void gather_kernel(
    const float* __restrict__ x,
    float* __restrict__ out)
{
    __shared__ float sx[16][Wn];
    __shared__ float sy[16][Wn];

    const int tid = threadIdx.x;
    const int h = blockIdx.x;
    const int b = blockIdx.y;
    const int z = blockIdx.z;

    #pragma unroll
    for (int i = 0; i < 8; i++) {
        const int idx = i * 256 + tid;            // 0..2047
        const int o = idx >> 6, w = idx & 63;
        const float v = d_coord[(size_t)(b * 32 + o) * NPOS + (h << 6) + w];
        if (o < 16) sx[o][w] = v;
        else        sy[o - 16][w] = v;
    }
    __syncthreads();

    const int ox = tid & 127;
    const int q  = (z << 1) | (tid >> 7);        // 0..3: 16-channel slab in group
    const int wq = ox >> 1;
    const int rx = ox & 1;

    #pragma unroll
    for (int ry = 0; ry < 2; ry++) {
        const int oy = 2 * h + ry;
        #pragma unroll
        for (int g = 0; g < Gn; g++) {
            const int j = g * 4 + ry * 2 + rx;
            const float ix = sx[j][wq];
            const float iy = sy[j][wq];
            const float xf = floorf(ix);
            const float yf = floorf(iy);
            const float wx = ix - xf;
            const float wy = iy - yf;
            const int xi = (int)xf;
            const int yi = (int)yf;
            const int x0 = min(max(xi, 0), Wn - 1);
            const int x1 = min(max(xi + 1, 0), Wn - 1);
            const int y0 = min(max(yi, 0), Hn - 1);
            const int y1 = min(max(yi + 1, 0), Hn - 1);
            const float w00 = (1.f - wx) * (1.f - wy);
            const float w01 = wx * (1.f - wy);
            const float w10 = (1.f - wx) * wy;
            const float w11 = wx * wy;
            const int o00 = y0 * Wn + x0;
            const int o01 = y0 * Wn + x1;
            const int o10 = y1 * Wn + x0;
            const int o11 = y1 * Wn + x1;

            const int cbase = b * Cn + g * 64 + q * 16;
            const float* xp = x + (size_t)cbase * NPOS;
            float* op = out + (((size_t)cbase * OH + oy) * OW + ox);

            #pragma unroll
            for (int kk = 0; kk < 16; kk += 8) {
                float v00[8], v01[8], v10[8], v11[8];
                #pragma unroll
                for (int k = 0; k < 8; k++) {
                    const float* p = xp + (size_t)(kk + k) * NPOS;
                    v00[k] = __ldg(p + o00);
                    v01[k] = __ldg(p + o01);
                    v10[k] = __ldg(p + o10);
                    v11[k] = __ldg(p + o11);
                }
                #pragma unroll
                for (int k = 0; k < 8; k++) {
                    op[(size_t)(kk + k) * (OH * OW)] =
                        w00 * v00[k] + w01 * v01[k] + w10 * v10[k] + w11 * v11[k];
                }
            }
        }
    }
}

extern "C" void kernel_launch(void* const* d_in, const int* in_sizes, int n_in,
                              void* d_out, int out_size) {
    const float* x    = (const float*)d_in[0];
    const float* Woff = (const float*)d_in[1];
    const float* boff = (const float*)d_in[2];
    float* out = (float*)d_out;

    dim3 gridA(64, Bn);
    offset_kernel<<<gridA, 256>>>(x, Woff, boff);

    dim3 gridB(Hn, Bn, 2);
    gather_kernel<<<gridB, 256>>>(x, out);
}

// round 6
// speedup vs baseline: 2.2078x; 1.1422x over previous
#include <cuda_runtime.h>
#include <cuda_bf16.h>
#include <cstdint>

// DySample: x(8,256,64,64), W_off(32,256), b_off(32) -> out(8,256,128,128), fp32.
//   A: offsets = W_off @ x + b_off folded into final sample coords -> 4MB scratch.
//   B: bilinear gather staged through smem (3 input rows cover all samples of an
//      output row-pair since |0.25*off + initpos| << 1), with global fallback.
// ix = w + (0.25*off_x + ipx), iy = h + (0.25*off_y + ipy);
// j = g*4 + ry*2 + rx; o_x = j, o_y = 16 + j; ipx = (j&1)?+.25:-.25, ipy = ((j>>1)&1)?+.25:-.25

#define Bn 8
#define Cn 256
#define Hn 64
#define Wn 64
#define Gn 4
#define NPOS 4096
#define OH 128
#define OW 128

typedef unsigned long long ull;

__device__ float d_coord[Bn * 32 * NPOS];   // 4 MB scratch

__device__ __forceinline__ void ffma2(ull &d, ull a, ull b) {
    asm("fma.rn.f32x2 %0, %1, %2, %0;" : "+l"(d) : "l"(a), "l"(b));
}
__device__ __forceinline__ ull pack2(float lo, float hi) {
    ull r;
    asm("mov.b64 %0, {%1, %2};" : "=l"(r) : "f"(lo), "f"(hi));
    return r;
}
__device__ __forceinline__ void unpack2(ull v, float &lo, float &hi) {
    asm("mov.b64 {%0, %1}, %2;" : "=f"(lo), "=f"(hi) : "l"(v));
}

// ---------------- Kernel A: offset GEMM, 8-way channel split ----------------
// grid (128, 8), 256 threads. Block = 32 positions; thread = (pos, cq), cq owns 32 ch.
__global__ __launch_bounds__(256) void offset_kernel(
    const float* __restrict__ x,
    const float* __restrict__ Woff,
    const float* __restrict__ boff)
{
    __shared__ __align__(16) char sraw[32768];
    ull (*Wp)[256] = reinterpret_cast<ull(*)[256]>(sraw);            // [16][256] 32KB
    float2 (*red)[8][32] = reinterpret_cast<float2(*)[8][32]>(sraw); // [16][8][32] 32KB

    const int tid  = threadIdx.x;
    const int b    = blockIdx.y;
    const int posl = tid & 31;
    const int cq   = tid >> 5;                 // 0..7 (warp-uniform)
    const int gpos = blockIdx.x * 32 + posl;

    #pragma unroll
    for (int i = 0; i < 16; i++) {
        const int idx = i * 256 + tid;
        const int p = idx >> 8, c = idx & 255;
        Wp[p][c] = pack2(Woff[p * Cn + c], Woff[(p + 16) * Cn + c]);
    }
    __syncthreads();

    ull acc[16];
    #pragma unroll
    for (int p = 0; p < 16; p++) acc[p] = 0ull;

    const float* xb = x + (size_t)b * Cn * NPOS + gpos;
    const int c0 = cq * 32;

    #pragma unroll 4
    for (int cc = 0; cc < 32; cc += 2) {
        const int c = c0 + cc;
        const float xv0 = __ldg(xb + (size_t)c * NPOS);
        const float xv1 = __ldg(xb + (size_t)(c + 1) * NPOS);
        const ull xp0 = pack2(xv0, xv0);
        const ull xp1 = pack2(xv1, xv1);
        #pragma unroll
        for (int p = 0; p < 16; p++) {
            ulonglong2 wv = *(const ulonglong2*)&Wp[p][c];
            ffma2(acc[p], wv.x, xp0);
            ffma2(acc[p], wv.y, xp1);
        }
    }
    __syncthreads();                      // Wp dead; reuse smem

    #pragma unroll
    for (int p = 0; p < 16; p++) {
        float lo, hi;
        unpack2(acc[p], lo, hi);
        red[p][cq][posl] = make_float2(lo, hi);
    }
    __syncthreads();

    // thread (pos, pp) finishes packs p = pp*2, pp*2+1
    const int pp = tid >> 5;
    const int w = gpos & 63;
    const int h = gpos >> 6;
    #pragma unroll
    for (int t = 0; t < 2; t++) {
        const int p = pp * 2 + t;
        float2 s = red[p][0][posl];
        #pragma unroll
        for (int q = 1; q < 8; q++) {
            float2 u = red[p][q][posl];
            s.x += u.x; s.y += u.y;
        }
        const float ipx = (p & 1) ? 0.25f : -0.25f;
        const float ipy = ((p >> 1) & 1) ? 0.25f : -0.25f;
        const float cx = (float)w + 0.25f * (s.x + __ldg(boff + p)) + ipx;
        const float cy = (float)h + 0.25f * (s.y + __ldg(boff + p + 16)) + ipy;
        d_coord[(size_t)(b * 32 + p) * NPOS + gpos]      = cx;
        d_coord[(size_t)(b * 32 + p + 16) * NPOS + gpos] = cy;
    }
}

// ---------------- Kernel B: smem-staged bilinear gather ----------------
// grid (64, 8, 8) = (h, b, g*2+half). 256 threads. Stage 3 rows x 32 ch in smem.
__global__ __launch_bounds__(256) void gather_kernel(
    const float* __restrict__ x,
    float* __restrict__ out)
{
    __shared__ float xs[3][32][64];     // 24 KB, [row][c][w]
    __shared__ float sxy[2][4][64];     // 2 KB,  [xy][jj][wq]

    const int tid  = threadIdx.x;
    const int h    = blockIdx.x;
    const int b    = blockIdx.y;
    const int g    = blockIdx.z >> 1;
    const int half = blockIdx.z & 1;

    // stage coords for this group's 4 j's
    #pragma unroll
    for (int i = 0; i < 2; i++) {
        const int lin = i * 256 + tid;        // 0..511
        const int w  = lin & 63;
        const int jj = (lin >> 6) & 3;
        const int xy = lin >> 8;
        sxy[xy][jj][w] =
            d_coord[(size_t)(b * 32 + g * 4 + jj + xy * 16) * NPOS + (h << 6) + w];
    }

    // stage 3 input rows (clamped) x 32 channels, float4 coalesced
    const int cstage = b * Cn + g * 64 + half * 32;
    #pragma unroll
    for (int i = 0; i < 6; i++) {
        const int lin = i * 256 + tid;        // 0..1535
        const int w4 = lin & 15;
        const int rr = (lin >> 4) % 3;
        const int c  = lin / 48;              // 0..31
        const int rowy = min(max(h - 1 + rr, 0), Hn - 1);
        const float4 v = __ldg((const float4*)(x
            + (((size_t)(cstage + c)) * Hn + rowy) * Wn) + w4);
        *(float4*)&xs[rr][c][w4 * 4] = v;
    }
    __syncthreads();

    const int ox    = tid & 127;
    const int chunk = tid >> 7;               // 0..1 -> 16 channels each
    const int wq = ox >> 1;
    const int rx = ox & 1;
    const int cbase = cstage + chunk * 16;

    #pragma unroll
    for (int ry = 0; ry < 2; ry++) {
        const int jj = ry * 2 + rx;
        const float ix = sxy[0][jj][wq];
        const float iy = sxy[1][jj][wq];
        const float xf = floorf(ix);
        const float yf = floorf(iy);
        const float wx = ix - xf;
        const float wy = iy - yf;
        const int xi = (int)xf;
        const int yi = (int)yf;
        const int y0 = min(max(yi, 0), Hn - 1);
        const int y1 = min(max(yi + 1, 0), Hn - 1);
        const int r0 = y0 - h + 1;
        const int r1 = y1 - h + 1;
        const int xc = min(max(xi, 0), Wn - 2);   // xc in [0,62]; read xc, xc+1
        const bool selL = (xi > Wn - 2);      // both corners clamp to 63
        const bool selR = (xi < 0);           // both corners clamp to 0
        const bool fast = ((unsigned)r0 <= 2u) && ((unsigned)r1 <= 2u);

        const float w1y = wy, w0y = 1.f - wy;
        const float w1x = wx, w0x = 1.f - wx;

        const int oy = 2 * h + ry;
        float* op = out + (((size_t)cbase * OH + oy) * OW + ox);

        if (__builtin_expect(fast, 1)) {
            #pragma unroll
            for (int k = 0; k < 16; k++) {
                const float* ra = &xs[r0][chunk * 16 + k][0];
                const float* rb = &xs[r1][chunk * 16 + k][0];
                const float a0 = ra[xc];
                const float a1 = ra[xc + 1];
                const float b0 = rb[xc];
                const float b1 = rb[xc + 1];
                const float aL = selL ? a1 : a0;
                const float aR = selR ? a0 : a1;
                const float bL = selL ? b1 : b0;
                const float bR = selR ? b0 : b1;
                const float top = aL * w0x + aR * w1x;
                const float bot = bL * w0x + bR * w1x;
                op[(size_t)k * (OH * OW)] = top * w0y + bot * w1y;
            }
        } else {
            const int x0 = min(max(xi, 0), Wn - 1);
            const int x1 = min(max(xi + 1, 0), Wn - 1);
            const int o00 = y0 * Wn + x0;
            const int o01 = y0 * Wn + x1;
            const int o10 = y1 * Wn + x0;
            const int o11 = y1 * Wn + x1;
            #pragma unroll
            for (int k = 0; k < 16; k++) {
                const float* p = x + (size_t)(cbase + k) * NPOS;
                const float v = (w0x * __ldg(p + o00) + w1x * __ldg(p + o01)) * w0y
                              + (w0x * __ldg(p + o10) + w1x * __ldg(p + o11)) * w1y;
                op[(size_t)k * (OH * OW)] = v;
            }
        }
    }
}

extern "C" void kernel_launch(void* const* d_in, const int* in_sizes, int n_in,
                              void* d_out, int out_size) {
    const float* x    = (const float*)d_in[0];
    const float* Woff = (const float*)d_in[1];
    const float* boff = (const float*)d_in[2];
    float* out = (float*)d_out;

    dim3 gridA(128, Bn);
    offset_kernel<<<gridA, 256>>>(x, Woff, boff);

    dim3 gridB(Hn, Bn, 8);
    gather_kernel<<<gridB, 256>>>(x, out);
}